// round 10
// baseline (speedup 1.0000x reference)
#include <cuda_runtime.h>
#include <cuda_fp16.h>
#include <cstdint>

#define N_NODES 50000
#define N_EDGES 800000
#define CH 128

#define SCAN_BLK 512
#define NSCAN_BLOCKS ((N_NODES + SCAN_BLK - 1) / SCAN_BLK)  // 98

// ---------------- device scratch (no allocations allowed) ----------------
__device__ int   g_is64;
__device__ int   g_deg[N_NODES];
__device__ int   g_rowptr[N_NODES + 1];
__device__ int   g_cursor[N_NODES];
__device__ int   g_csr[N_EDGES];
__device__ int   g_blk_agg[NSCAN_BLOCKS];
__device__ int   g_blk_inc[NSCAN_BLOCKS];
__device__ volatile int g_blk_flag[NSCAN_BLOCKS];  // 0 reset, 1 agg ready, 2 inclusive ready
__device__ float g_invdeg[N_NODES];
__device__ __half g_xH [(size_t)N_NODES * CH];   // fp16 activations (layer input 0)
__device__ __half g_hHA[(size_t)N_NODES * CH];   // fp16 H ping
__device__ __half g_hHB[(size_t)N_NODES * CH];   // fp16 H pong
// weights split fp16 hi/lo, ORIGINAL [k][n] layout: [layer][WlH, WlL, WrH, WrL]
__device__ __half g_wS[3][4][128 * 128];

// ---------------- helpers ----------------
__device__ __forceinline__ uint32_t smem_u32(const void* p) {
    uint32_t a;
    asm("{ .reg .u64 t; cvta.to.shared.u64 t, %1; cvt.u32.u64 %0, t; }"
        : "=r"(a) : "l"(p));
    return a;
}
__device__ __forceinline__ uint32_t h2pack(float a, float b) {
    return (uint32_t)__half_as_ushort(__float2half_rn(a)) |
           ((uint32_t)__half_as_ushort(__float2half_rn(b)) << 16);
}
__device__ __forceinline__ float2 h2unpack(uint32_t v) {
    __half2 h = *(__half2*)&v;
    return __half22float2(h);
}

#define MMA_F16(d, a, b0, b1) \
    asm volatile("mma.sync.aligned.m16n8k16.row.col.f32.f16.f16.f32 " \
        "{%0,%1,%2,%3}, {%4,%5,%6,%7}, {%8,%9}, {%0,%1,%2,%3};" \
        : "+f"((d)[0]), "+f"((d)[1]), "+f"((d)[2]), "+f"((d)[3]) \
        : "r"((a)[0]), "r"((a)[1]), "r"((a)[2]), "r"((a)[3]), "r"(b0), "r"(b1))

// A fragment: m16k16 from [m][k] tile with 256B rows, per-row ((m&7)<<4) swizzle
__device__ __forceinline__ void ldmA256(uint32_t a[4], uint32_t base, int mbase,
                                        int k0, int lane) {
    int t = lane >> 3, r = lane & 7;
    int m = mbase + (t & 1) * 8 + r;
    int kb = k0 + (t >> 1) * 8;
    uint32_t addr = base + (uint32_t)(m * 256) +
                    (uint32_t)((kb * 2) ^ ((m & 7) << 4));
    asm volatile("ldmatrix.sync.aligned.m8n8.x4.shared.b16 {%0,%1,%2,%3}, [%4];"
                 : "=r"(a[0]), "=r"(a[1]), "=r"(a[2]), "=r"(a[3]) : "r"(addr));
}
// B fragments: two n8 tiles of k16 from [k][n] tile (256B rows, swizzled), trans
__device__ __forceinline__ void ldmB(uint32_t b[4], uint32_t base, int k0,
                                     int nb, int lane) {
    int t = lane >> 3, r = lane & 7;
    int k = k0 + (t & 1) * 8 + r;
    int n = nb + (t >> 1) * 8;
    uint32_t addr = base + (uint32_t)(k * 256) +
                    (uint32_t)((n * 2) ^ ((k & 7) << 4));
    asm volatile("ldmatrix.sync.aligned.m8n8.x4.trans.shared.b16 {%0,%1,%2,%3}, [%4];"
                 : "=r"(b[0]), "=r"(b[1]), "=r"(b[2]), "=r"(b[3]) : "r"(addr));
}

// ---------------- init: deg zero + out=bh + flag reset + detect + conversions ----------
#define WCONV_N (3 * 2 * 128 * 128)               // 98304 weight elements
#define XCONV_N (N_NODES * CH / 2)                // 3.2M x-pairs
__global__ void init_kernel(const float* __restrict__ Wl0, const float* __restrict__ Wr0,
                            const float* __restrict__ Wl1, const float* __restrict__ Wr1,
                            const float* __restrict__ Wl2, const float* __restrict__ Wr2,
                            const float* __restrict__ x, const float* __restrict__ bh,
                            float* __restrict__ out, const unsigned* __restrict__ w) {
    int id = blockIdx.x * blockDim.x + threadIdx.x;
    if (id < N_NODES) { g_deg[id] = 0; out[id] = bh[0]; }
    if (id < NSCAN_BLOCKS) g_blk_flag[id] = 0;
    if (blockIdx.x == 0) {
        __shared__ int any32;
        if (threadIdx.x == 0) any32 = 0;
        __syncthreads();
        for (int j = threadIdx.x; j < 1024; j += blockDim.x) {
            if (w[2 * j + 1] != 0u) any32 = 1;  // benign race
        }
        __syncthreads();
        if (threadIdx.x == 0) g_is64 = any32 ? 0 : 1;
    }
    if (id < WCONV_N) {
        const float* W[3][2] = {{Wl0, Wr0}, {Wl1, Wr1}, {Wl2, Wr2}};
        int l = id / 32768;
        int rem = id % 32768;
        int mat = rem / 16384;
        int e = rem % 16384;
        float wv = W[l][mat][e];
        __half hi = __float2half_rn(wv);
        __half lo = __float2half_rn(wv - __half2float(hi));
        g_wS[l][mat * 2 + 0][e] = hi;
        g_wS[l][mat * 2 + 1][e] = lo;
    }
    int xi = id - WCONV_N;
    if (xi >= 0 && xi < XCONV_N) {
        float2 v = ((const float2*)x)[xi];
        ((uint32_t*)g_xH)[xi] = h2pack(v.x, v.y);
    }
}

__device__ __forceinline__ int load_edge(const void* ei, int idx, int is64) {
    if (is64) return (int)((const long long*)ei)[idx];
    return ((const int*)ei)[idx];
}

__global__ void deg_kernel(const void* __restrict__ ei) {
    int e = blockIdx.x * blockDim.x + threadIdx.x;
    if (e >= N_EDGES) return;
    int d = load_edge(ei, N_EDGES + e, g_is64);
    atomicAdd(&g_deg[d], 1);
}

// ---------------- single-pass decoupled-lookback scan ----------------
__global__ void scan_kernel() {
    int b = blockIdx.x, t = threadIdx.x;
    int i = b * SCAN_BLK + t;
    int lane = t & 31, wid = t >> 5;
    int d = (i < N_NODES) ? g_deg[i] : 0;
    // warp inclusive scan
    int incl = d;
#pragma unroll
    for (int off = 1; off < 32; off <<= 1) {
        int u = __shfl_up_sync(0xFFFFFFFFu, incl, off);
        if (lane >= off) incl += u;
    }
    __shared__ int wsum[SCAN_BLK / 32];
    __shared__ int wexcl[SCAN_BLK / 32];
    __shared__ int s_excl;
    if (lane == 31) wsum[wid] = incl;
    __syncthreads();
    if (t == 0) {
        int run = 0;
#pragma unroll
        for (int w = 0; w < SCAN_BLK / 32; w++) { wexcl[w] = run; run += wsum[w]; }
        int tot = run;
        int ex = 0;
        if (b > 0) {
            g_blk_agg[b] = tot;
            __threadfence();
            g_blk_flag[b] = 1;
            for (int p = b - 1; p >= 0;) {
                int f;
                do { f = g_blk_flag[p]; } while (f == 0);
                __threadfence();
                if (f == 2) { ex += g_blk_inc[p]; break; }
                ex += g_blk_agg[p];
                p--;
            }
        }
        g_blk_inc[b] = ex + tot;
        __threadfence();
        g_blk_flag[b] = 2;
        s_excl = ex;
        if (b == NSCAN_BLOCKS - 1) g_rowptr[N_NODES] = ex + tot;
    }
    __syncthreads();
    if (i < N_NODES) {
        int exi = s_excl + wexcl[wid] + (incl - d);
        g_rowptr[i] = exi;
        g_cursor[i] = exi;
        g_invdeg[i] = (d > 0) ? (1.0f / (float)d) : 0.0f;
    }
}

__global__ void fill_kernel(const void* __restrict__ ei) {
    int e = blockIdx.x * blockDim.x + threadIdx.x;
    if (e >= N_EDGES) return;
    int is64 = g_is64;
    int s = load_edge(ei, e, is64);
    int d = load_edge(ei, N_EDGES + e, is64);
    int pos = atomicAdd(&g_cursor[d], 1);
    g_csr[pos] = s;
}

// ---------------- fused agg + dual GEMM (+ optional head) ----------------
// Block = 128 nodes. Phase 1: gather mean-agg + copy H rows into SMEM (fp16,
// 256B rows, per-row swizzle). Phase 2: W staged in 4 chunks of 32 k-rows,
// 8 warps (4M x 2N), warp tile m32 x n64, fp16 split weights (2 products).
#define FG_SA 0                  // [128][128] fp16 agg     = 32 KB
#define FG_SH 32768              // [128][128] fp16 h       = 32 KB
#define FG_SW 65536              // 4 mats x [32][128] fp16 = 32 KB
#define FG_SMEM 98304

__global__ void __launch_bounds__(256, 2)
fused_gemm_kernel(const __half* __restrict__ H,
                  const __half* __restrict__ WS,  // [4][128*128] k-major
                  const float* __restrict__ bl, __half* __restrict__ hHOut,
                  const float* __restrict__ Wh, float* __restrict__ out,
                  int write_head) {
    extern __shared__ char smem[];
    uint32_t sb = smem_u32(smem);
    int tid = threadIdx.x;
    int lane = tid & 31;
    int warp = tid >> 5;
    int row0 = blockIdx.x * 128;

    // ---- phase 1: 16 nodes per warp -> agg into sA, copy h into sH ----
    for (int i = 0; i < 16; i++) {
        int r = warp * 16 + i;
        int node = row0 + r;
        uint32_t off = (uint32_t)(r * 256) + (uint32_t)((lane * 8) ^ ((r & 7) << 4));
        if (node < N_NODES) {
            const size_t laneoff = (size_t)(lane * 4);
            // copy h row
            uint2 hv = *(const uint2*)(H + (size_t)node * CH + laneoff);
            *(uint2*)(smem + FG_SH + off) = hv;
            // gather mean aggregation
            int beg = g_rowptr[node];
            int n = g_rowptr[node + 1] - beg;
            float4 acc0 = make_float4(0.f, 0.f, 0.f, 0.f);
            float4 acc1 = acc0, acc2 = acc0, acc3 = acc0;
            for (int base = 0; base < n; base += 32) {
                int cnt = n - base;
                if (cnt > 32) cnt = 32;
                int myidx = (lane < cnt) ? g_csr[beg + base + lane] : 0;
                int j = 0;
                for (; j + 4 <= cnt; j += 4) {
                    int s0 = __shfl_sync(0xFFFFFFFFu, myidx, j + 0);
                    int s1 = __shfl_sync(0xFFFFFFFFu, myidx, j + 1);
                    int s2 = __shfl_sync(0xFFFFFFFFu, myidx, j + 2);
                    int s3 = __shfl_sync(0xFFFFFFFFu, myidx, j + 3);
                    uint2 r0 = *(const uint2*)(H + (size_t)s0 * CH + laneoff);
                    uint2 r1 = *(const uint2*)(H + (size_t)s1 * CH + laneoff);
                    uint2 r2 = *(const uint2*)(H + (size_t)s2 * CH + laneoff);
                    uint2 r3 = *(const uint2*)(H + (size_t)s3 * CH + laneoff);
#define ACC(q, rr) do { float2 _a = h2unpack(rr.x), _b = h2unpack(rr.y); \
                    q.x += _a.x; q.y += _a.y; q.z += _b.x; q.w += _b.y; } while (0)
                    ACC(acc0, r0); ACC(acc1, r1); ACC(acc2, r2); ACC(acc3, r3);
                }
                for (; j < cnt; j++) {
                    int s0 = __shfl_sync(0xFFFFFFFFu, myidx, j);
                    uint2 r0 = *(const uint2*)(H + (size_t)s0 * CH + laneoff);
                    ACC(acc0, r0);
#undef ACC
                }
            }
            acc0.x += acc1.x + acc2.x + acc3.x;
            acc0.y += acc1.y + acc2.y + acc3.y;
            acc0.z += acc1.z + acc2.z + acc3.z;
            acc0.w += acc1.w + acc2.w + acc3.w;
            float s = g_invdeg[node];
            uint2 p;
            p.x = h2pack(acc0.x * s, acc0.y * s);
            p.y = h2pack(acc0.z * s, acc0.w * s);
            *(uint2*)(smem + FG_SA + off) = p;
        } else {
            uint2 z = make_uint2(0u, 0u);
            *(uint2*)(smem + FG_SH + off) = z;
            *(uint2*)(smem + FG_SA + off) = z;
        }
    }

    // ---- phase 2: GEMM over 4 W chunks of 32 k-rows ----
    int warpM = warp & 3;
    int warpN = warp >> 2;
    int mwbase = warpM * 32;
    int n0 = warpN * 64;

    float acc[2][8][4];
#pragma unroll
    for (int mi = 0; mi < 2; mi++)
#pragma unroll
        for (int j = 0; j < 8; j++)
#pragma unroll
            for (int q = 0; q < 4; q++) acc[mi][j][q] = 0.f;

    for (int chunk = 0; chunk < 4; chunk++) {
        __syncthreads();  // protect sW (and order phase-1 writes on first iter)
        // stage W chunk: 4 mats x 32 k-rows x 16 uint4
        for (int idx = tid; idx < 2048; idx += 256) {
            int mat = idx >> 9;
            int rem = idx & 511;
            int k = rem >> 4;
            int u = rem & 15;
            uint4 v = *(const uint4*)(WS + mat * 16384 + (chunk * 32 + k) * 128 + u * 8);
            uint32_t b = (uint32_t)(k * 256) + (uint32_t)((u * 16) ^ ((k & 7) << 4));
            *(uint4*)(smem + FG_SW + mat * 8192 + b) = v;
        }
        __syncthreads();
#pragma unroll
        for (int k16 = 0; k16 < 2; k16++) {
            int kg = chunk * 32 + k16 * 16;   // global k for A tiles
            int kw = k16 * 16;                // k within W chunk
#pragma unroll
            for (int grp = 0; grp < 2; grp++) {   // 0: agg x Wl, 1: h x Wr
                uint32_t a[2][4];
                uint32_t abase = sb + (grp ? FG_SH : FG_SA);
                ldmA256(a[0], abase, mwbase, kg, lane);
                ldmA256(a[1], abase, mwbase + 16, kg, lane);
#pragma unroll
                for (int j = 0; j < 4; j++) {
                    uint32_t bh_[4], blo[4];
                    ldmB(bh_, sb + FG_SW + (grp * 2 + 0) * 8192, kw, n0 + j * 16, lane);
                    ldmB(blo, sb + FG_SW + (grp * 2 + 1) * 8192, kw, n0 + j * 16, lane);
#pragma unroll
                    for (int mi = 0; mi < 2; mi++) {
                        MMA_F16(acc[mi][2 * j],     a[mi], bh_[0], bh_[1]);
                        MMA_F16(acc[mi][2 * j + 1], a[mi], bh_[2], bh_[3]);
                        MMA_F16(acc[mi][2 * j],     a[mi], blo[0], blo[1]);
                        MMA_F16(acc[mi][2 * j + 1], a[mi], blo[2], blo[3]);
                    }
                }
            }
        }
    }

    // ---- epilogue ----
    int g = lane >> 2, tg = lane & 3;
    if (!write_head) {
#pragma unroll
        for (int mi = 0; mi < 2; mi++) {
            int r1 = row0 + mwbase + mi * 16 + g;
#pragma unroll
            for (int j = 0; j < 8; j++) {
                int col = n0 + j * 8 + tg * 2;
                float2 bb = *(const float2*)(bl + col);
                float o0 = fmaxf(acc[mi][j][0] + bb.x, 0.f);
                float o1 = fmaxf(acc[mi][j][1] + bb.y, 0.f);
                float o2 = fmaxf(acc[mi][j][2] + bb.x, 0.f);
                float o3 = fmaxf(acc[mi][j][3] + bb.y, 0.f);
                if (r1 < N_NODES)
                    *(uint32_t*)(hHOut + (size_t)r1 * CH + col) = h2pack(o0, o1);
                if (r1 + 8 < N_NODES)
                    *(uint32_t*)(hHOut + (size_t)(r1 + 8) * CH + col) = h2pack(o2, o3);
            }
        }
    } else {
        // fused head: partial = sum_col relu(h)*Wh[col]; out pre-initialized to bh
#pragma unroll
        for (int mi = 0; mi < 2; mi++) {
            int r1 = row0 + mwbase + mi * 16 + g;
            float p0 = 0.f, p2 = 0.f;
#pragma unroll
            for (int j = 0; j < 8; j++) {
                int col = n0 + j * 8 + tg * 2;
                float2 bb = *(const float2*)(bl + col);
                float2 wh = *(const float2*)(Wh + col);
                float o0 = fmaxf(acc[mi][j][0] + bb.x, 0.f);
                float o1 = fmaxf(acc[mi][j][1] + bb.y, 0.f);
                float o2 = fmaxf(acc[mi][j][2] + bb.x, 0.f);
                float o3 = fmaxf(acc[mi][j][3] + bb.y, 0.f);
                p0 += o0 * wh.x + o1 * wh.y;
                p2 += o2 * wh.x + o3 * wh.y;
            }
            p0 += __shfl_xor_sync(0xFFFFFFFFu, p0, 1);
            p0 += __shfl_xor_sync(0xFFFFFFFFu, p0, 2);
            p2 += __shfl_xor_sync(0xFFFFFFFFu, p2, 1);
            p2 += __shfl_xor_sync(0xFFFFFFFFu, p2, 2);
            if (tg == 0) {
                if (r1 < N_NODES) atomicAdd(out + r1, p0);
                if (r1 + 8 < N_NODES) atomicAdd(out + r1 + 8, p2);
            }
        }
    }
}

// ---------------- launch ----------------
extern "C" void kernel_launch(void* const* d_in, const int* in_sizes, int n_in,
                              void* d_out, int out_size) {
    const float* x  = (const float*)d_in[0];
    const void*  ei = d_in[1];
    const float* Wl[3] = {(const float*)d_in[2], (const float*)d_in[5], (const float*)d_in[8]};
    const float* Wr[3] = {(const float*)d_in[3], (const float*)d_in[6], (const float*)d_in[9]};
    const float* bl[3] = {(const float*)d_in[4], (const float*)d_in[7], (const float*)d_in[10]};
    const float* Wh = (const float*)d_in[11];
    const float* bh = (const float*)d_in[12];
    float* out = (float*)d_out;

    cudaFuncSetAttribute(fused_gemm_kernel, cudaFuncAttributeMaxDynamicSharedMemorySize,
                         FG_SMEM);

    void *pW, *pXH, *pHA, *pHB;
    cudaGetSymbolAddress(&pW, g_wS);
    cudaGetSymbolAddress(&pXH, g_xH);
    cudaGetSymbolAddress(&pHA, g_hHA);
    cudaGetSymbolAddress(&pHB, g_hHB);
    const __half* wS = (const __half*)pW;

    init_kernel<<<(WCONV_N + XCONV_N + 255) / 256, 256>>>(
        Wl[0], Wr[0], Wl[1], Wr[1], Wl[2], Wr[2], x, bh, out, (const unsigned*)ei);
    deg_kernel<<<(N_EDGES + 255) / 256, 256>>>(ei);
    scan_kernel<<<NSCAN_BLOCKS, SCAN_BLK>>>();
    fill_kernel<<<(N_EDGES + 255) / 256, 256>>>(ei);

    const int gemm_grid = (N_NODES + 127) / 128;  // 391
    const __half* hH_in[3] = {(__half*)pXH, (__half*)pHA, (__half*)pHB};
    __half* hH_out[3] = {(__half*)pHA, (__half*)pHB, (__half*)pHA};

    for (int l = 0; l < 3; l++) {
        fused_gemm_kernel<<<gemm_grid, 256, FG_SMEM>>>(
            hH_in[l], wS + (size_t)l * 4 * 16384, bl[l], hH_out[l],
            Wh, out, (l == 2) ? 1 : 0);
    }
}

// round 11
// speedup vs baseline: 1.4038x; 1.4038x over previous
#include <cuda_runtime.h>
#include <cuda_fp16.h>
#include <cstdint>

#define N_NODES 50000
#define N_EDGES 800000
#define CH 128

#define SCAN_BLK 512
#define NSCAN_BLOCKS ((N_NODES + SCAN_BLK - 1) / SCAN_BLK)  // 98

// ---------------- device scratch (no allocations allowed) ----------------
__device__ int   g_is64;
__device__ int   g_deg[N_NODES];
__device__ int   g_rowptr[N_NODES + 1];
__device__ int   g_cursor[N_NODES];
__device__ int   g_csr[N_EDGES];
__device__ int   g_blk_agg[NSCAN_BLOCKS];
__device__ int   g_blk_inc[NSCAN_BLOCKS];
__device__ volatile int g_blk_flag[NSCAN_BLOCKS];  // 0 reset, 1 agg ready, 2 inclusive ready
__device__ float g_invdeg[N_NODES];
__device__ __half g_xH [(size_t)N_NODES * CH];   // fp16 activations (layer input 0)
__device__ __half g_aggH[(size_t)N_NODES * CH];
__device__ __half g_hHA[(size_t)N_NODES * CH];   // fp16 H ping
__device__ __half g_hHB[(size_t)N_NODES * CH];   // fp16 H pong
// weights split fp16 hi/lo, ORIGINAL [k][n] layout: [layer][WlH, WlL, WrH, WrL]
__device__ __half g_wS[3][4][128 * 128];

// ---------------- helpers ----------------
__device__ __forceinline__ uint32_t smem_u32(const void* p) {
    uint32_t a;
    asm("{ .reg .u64 t; cvta.to.shared.u64 t, %1; cvt.u32.u64 %0, t; }"
        : "=r"(a) : "l"(p));
    return a;
}
__device__ __forceinline__ uint32_t h2pack(float a, float b) {
    return (uint32_t)__half_as_ushort(__float2half_rn(a)) |
           ((uint32_t)__half_as_ushort(__float2half_rn(b)) << 16);
}
__device__ __forceinline__ float2 h2unpack(uint32_t v) {
    __half2 h = *(__half2*)&v;
    return __half22float2(h);
}

#define MMA_F16(d, a, b0, b1) \
    asm volatile("mma.sync.aligned.m16n8k16.row.col.f32.f16.f16.f32 " \
        "{%0,%1,%2,%3}, {%4,%5,%6,%7}, {%8,%9}, {%0,%1,%2,%3};" \
        : "+f"((d)[0]), "+f"((d)[1]), "+f"((d)[2]), "+f"((d)[3]) \
        : "r"((a)[0]), "r"((a)[1]), "r"((a)[2]), "r"((a)[3]), "r"(b0), "r"(b1))

// A fragment: m16k16 from [m][k] tile (128B rows, SW128 swizzle)
__device__ __forceinline__ void ldmA(uint32_t a[4], uint32_t base, int mbase,
                                     int k0, int lane) {
    int t = lane >> 3, r = lane & 7;
    int m = mbase + (t & 1) * 8 + r;
    int kb = k0 + (t >> 1) * 8;
    uint32_t addr = base + (((uint32_t)(m * 128 + kb * 2)) ^ (uint32_t)((m & 7) << 4));
    asm volatile("ldmatrix.sync.aligned.m8n8.x4.shared.b16 {%0,%1,%2,%3}, [%4];"
                 : "=r"(a[0]), "=r"(a[1]), "=r"(a[2]), "=r"(a[3]) : "r"(addr));
}
// B fragments: two n8 tiles of k16 from [k][n] tile (256B rows, swizzled), trans
__device__ __forceinline__ void ldmB(uint32_t b[4], uint32_t base, int k0,
                                     int nb, int lane) {
    int t = lane >> 3, r = lane & 7;
    int k = k0 + (t & 1) * 8 + r;
    int n = nb + (t >> 1) * 8;
    uint32_t addr = base + (((uint32_t)(k * 256 + n * 2)) ^ (uint32_t)((k & 7) << 4));
    asm volatile("ldmatrix.sync.aligned.m8n8.x4.trans.shared.b16 {%0,%1,%2,%3}, [%4];"
                 : "=r"(b[0]), "=r"(b[1]), "=r"(b[2]), "=r"(b[3]) : "r"(addr));
}

// ---------------- init: deg zero + out=bh + flag reset + detect + conversions ----------
#define WCONV_N (3 * 2 * 128 * 128)               // 98304 weight elements
#define XCONV_N (N_NODES * CH / 2)                // 3.2M x-pairs
__global__ void init_kernel(const float* __restrict__ Wl0, const float* __restrict__ Wr0,
                            const float* __restrict__ Wl1, const float* __restrict__ Wr1,
                            const float* __restrict__ Wl2, const float* __restrict__ Wr2,
                            const float* __restrict__ x, const float* __restrict__ bh,
                            float* __restrict__ out, const unsigned* __restrict__ w) {
    int id = blockIdx.x * blockDim.x + threadIdx.x;
    if (id < N_NODES) { g_deg[id] = 0; out[id] = bh[0]; }
    if (id < NSCAN_BLOCKS) g_blk_flag[id] = 0;
    if (blockIdx.x == 0) {
        __shared__ int any32;
        if (threadIdx.x == 0) any32 = 0;
        __syncthreads();
        for (int j = threadIdx.x; j < 1024; j += blockDim.x) {
            if (w[2 * j + 1] != 0u) any32 = 1;  // benign race
        }
        __syncthreads();
        if (threadIdx.x == 0) g_is64 = any32 ? 0 : 1;
    }
    if (id < WCONV_N) {
        const float* W[3][2] = {{Wl0, Wr0}, {Wl1, Wr1}, {Wl2, Wr2}};
        int l = id / 32768;
        int rem = id % 32768;
        int mat = rem / 16384;
        int e = rem % 16384;
        float wv = W[l][mat][e];
        __half hi = __float2half_rn(wv);
        __half lo = __float2half_rn(wv - __half2float(hi));
        g_wS[l][mat * 2 + 0][e] = hi;
        g_wS[l][mat * 2 + 1][e] = lo;
    }
    int xi = id - WCONV_N;
    if (xi >= 0 && xi < XCONV_N) {
        float2 v = ((const float2*)x)[xi];
        ((uint32_t*)g_xH)[xi] = h2pack(v.x, v.y);
    }
}

__device__ __forceinline__ int load_edge(const void* ei, int idx, int is64) {
    if (is64) return (int)((const long long*)ei)[idx];
    return ((const int*)ei)[idx];
}

__global__ void deg_kernel(const void* __restrict__ ei) {
    int e = blockIdx.x * blockDim.x + threadIdx.x;
    if (e >= N_EDGES) return;
    int d = load_edge(ei, N_EDGES + e, g_is64);
    atomicAdd(&g_deg[d], 1);
}

// ---------------- single-pass decoupled-lookback scan ----------------
__global__ void scan_kernel() {
    int b = blockIdx.x, t = threadIdx.x;
    int i = b * SCAN_BLK + t;
    int lane = t & 31, wid = t >> 5;
    int d = (i < N_NODES) ? g_deg[i] : 0;
    int incl = d;
#pragma unroll
    for (int off = 1; off < 32; off <<= 1) {
        int u = __shfl_up_sync(0xFFFFFFFFu, incl, off);
        if (lane >= off) incl += u;
    }
    __shared__ int wsum[SCAN_BLK / 32];
    __shared__ int wexcl[SCAN_BLK / 32];
    __shared__ int s_excl;
    if (lane == 31) wsum[wid] = incl;
    __syncthreads();
    if (t == 0) {
        int run = 0;
#pragma unroll
        for (int w = 0; w < SCAN_BLK / 32; w++) { wexcl[w] = run; run += wsum[w]; }
        int tot = run;
        int ex = 0;
        if (b > 0) {
            g_blk_agg[b] = tot;
            __threadfence();
            g_blk_flag[b] = 1;
            for (int p = b - 1; p >= 0;) {
                int f;
                do { f = g_blk_flag[p]; } while (f == 0);
                __threadfence();
                if (f == 2) { ex += g_blk_inc[p]; break; }
                ex += g_blk_agg[p];
                p--;
            }
        }
        g_blk_inc[b] = ex + tot;
        __threadfence();
        g_blk_flag[b] = 2;
        s_excl = ex;
        if (b == NSCAN_BLOCKS - 1) g_rowptr[N_NODES] = ex + tot;
    }
    __syncthreads();
    if (i < N_NODES) {
        int exi = s_excl + wexcl[wid] + (incl - d);
        g_rowptr[i] = exi;
        g_cursor[i] = exi;
        g_invdeg[i] = (d > 0) ? (1.0f / (float)d) : 0.0f;
    }
}

__global__ void fill_kernel(const void* __restrict__ ei) {
    int e = blockIdx.x * blockDim.x + threadIdx.x;
    if (e >= N_EDGES) return;
    int is64 = g_is64;
    int s = load_edge(ei, e, is64);
    int d = load_edge(ei, N_EDGES + e, is64);
    int pos = atomicAdd(&g_cursor[d], 1);
    g_csr[pos] = s;
}

// ---------------- aggregation: one warp per node, coalesced idx + MLP8 ----------------
__global__ void agg_kernel(const __half* __restrict__ H) {
    int gt = blockIdx.x * blockDim.x + threadIdx.x;
    int node = gt >> 5;
    int lane = gt & 31;
    if (node >= N_NODES) return;
    int beg = g_rowptr[node];
    int n = g_rowptr[node + 1] - beg;

    float4 acc[8];
#pragma unroll
    for (int q = 0; q < 8; q++) acc[q] = make_float4(0.f, 0.f, 0.f, 0.f);

    const size_t laneoff = (size_t)(lane * 4);
    for (int base = 0; base < n; base += 32) {
        int cnt = n - base;
        if (cnt > 32) cnt = 32;
        int myidx = (lane < cnt) ? g_csr[beg + base + lane] : 0;
        int j = 0;
        for (; j + 8 <= cnt; j += 8) {
            int s0 = __shfl_sync(0xFFFFFFFFu, myidx, j + 0);
            int s1 = __shfl_sync(0xFFFFFFFFu, myidx, j + 1);
            int s2 = __shfl_sync(0xFFFFFFFFu, myidx, j + 2);
            int s3 = __shfl_sync(0xFFFFFFFFu, myidx, j + 3);
            int s4 = __shfl_sync(0xFFFFFFFFu, myidx, j + 4);
            int s5 = __shfl_sync(0xFFFFFFFFu, myidx, j + 5);
            int s6 = __shfl_sync(0xFFFFFFFFu, myidx, j + 6);
            int s7 = __shfl_sync(0xFFFFFFFFu, myidx, j + 7);
            uint2 r0 = *(const uint2*)(H + (size_t)s0 * CH + laneoff);
            uint2 r1 = *(const uint2*)(H + (size_t)s1 * CH + laneoff);
            uint2 r2 = *(const uint2*)(H + (size_t)s2 * CH + laneoff);
            uint2 r3 = *(const uint2*)(H + (size_t)s3 * CH + laneoff);
            uint2 r4 = *(const uint2*)(H + (size_t)s4 * CH + laneoff);
            uint2 r5 = *(const uint2*)(H + (size_t)s5 * CH + laneoff);
            uint2 r6 = *(const uint2*)(H + (size_t)s6 * CH + laneoff);
            uint2 r7 = *(const uint2*)(H + (size_t)s7 * CH + laneoff);
#define ACC(q, r) do { float2 _a = h2unpack(r.x), _b = h2unpack(r.y); \
            acc[q].x += _a.x; acc[q].y += _a.y; acc[q].z += _b.x; acc[q].w += _b.y; } while (0)
            ACC(0, r0); ACC(1, r1); ACC(2, r2); ACC(3, r3);
            ACC(4, r4); ACC(5, r5); ACC(6, r6); ACC(7, r7);
        }
        for (; j < cnt; j++) {
            int s0 = __shfl_sync(0xFFFFFFFFu, myidx, j);
            uint2 r0 = *(const uint2*)(H + (size_t)s0 * CH + laneoff);
            ACC(0, r0);
#undef ACC
        }
    }
#pragma unroll
    for (int q = 1; q < 8; q++) {
        acc[0].x += acc[q].x; acc[0].y += acc[q].y;
        acc[0].z += acc[q].z; acc[0].w += acc[q].w;
    }
    float s = g_invdeg[node];
    uint2 p;
    p.x = h2pack(acc[0].x * s, acc[0].y * s);
    p.y = h2pack(acc[0].z * s, acc[0].w * s);
    *(uint2*)(g_aggH + (size_t)node * CH + laneoff) = p;
}

// ---------------- tensor-core fused dual GEMM via mma.sync (fp16) ----------------
// Out = relu(Agg@Wl + bl + H@Wr); weights split exact: x*(wh+wl), 2 products.
// CTA: 128x128 tile; 8 warps (4M x 2N), warp tile m32 x n64; K chunk 64.
// Last layer (write_head=1): epilogue computes logits directly into out.
#define SM_A 0                 // 2 arrays x [128][64] fp16 = 32 KB
#define SM_W 32768             // 4 mats   x [64][128] fp16 = 64 KB
#define TC_SMEM 98304

__global__ void __launch_bounds__(256, 2)
tc_gemm_kernel(const __half* __restrict__ aggH, const __half* __restrict__ hH,
               const __half* __restrict__ WS,  // [4][128*128] k-major: WlH,WlL,WrH,WrL
               const float* __restrict__ bl, __half* __restrict__ hHOut,
               const float* __restrict__ Wh, float* __restrict__ out,
               int write_head) {
    extern __shared__ char smem[];
    uint32_t sb = smem_u32(smem);
    int tid = threadIdx.x;
    int lane = tid & 31;
    int warp = tid >> 5;
    int warpM = warp & 3;         // 0..3 -> m offset *32
    int warpN = warp >> 2;        // 0..1 -> n offset *64
    int row0 = blockIdx.x * 128;
    int mwbase = warpM * 32;
    int n0 = warpN * 64;

    const __half* Asrc[2] = {aggH, hH};

    float acc[2][8][4];
#pragma unroll
    for (int mi = 0; mi < 2; mi++)
#pragma unroll
        for (int j = 0; j < 8; j++)
#pragma unroll
            for (int q = 0; q < 4; q++) acc[mi][j][q] = 0.f;

    for (int kc = 0; kc < 128; kc += 64) {
        __syncthreads();
        // stage A: 2 arrays x 128 rows x 8 units(16B)
        for (int idx = tid; idx < 2048; idx += 256) {
            int arr = idx >> 10;
            int rem = idx & 1023;
            int r = rem >> 3;
            int u = rem & 7;
            int row = row0 + r;
            uint4 v = make_uint4(0u, 0u, 0u, 0u);
            if (row < N_NODES)
                v = *(const uint4*)(Asrc[arr] + (size_t)row * CH + kc + u * 8);
            uint32_t b = (uint32_t)(r * 128 + u * 16) ^ (uint32_t)((r & 7) << 4);
            *(uint4*)(smem + SM_A + arr * 16384 + b) = v;
        }
        // stage W: 4 mats x 64 k-rows x 16 units
        for (int idx = tid; idx < 4096; idx += 256) {
            int mat = idx >> 10;
            int rem = idx & 1023;
            int k = rem >> 4;
            int u = rem & 15;
            uint4 v = *(const uint4*)(WS + mat * 16384 + (kc + k) * 128 + u * 8);
            uint32_t b = (uint32_t)(k * 256 + u * 16) ^ (uint32_t)((k & 7) << 4);
            *(uint4*)(smem + SM_W + mat * 16384 + b) = v;
        }
        __syncthreads();

#pragma unroll
        for (int k16 = 0; k16 < 4; k16++) {
            int k0 = k16 * 16;
#pragma unroll
            for (int grp = 0; grp < 2; grp++) {   // 0: agg x Wl, 1: h x Wr
                uint32_t a[2][4];
                ldmA(a[0], sb + SM_A + grp * 16384, mwbase, k0, lane);
                ldmA(a[1], sb + SM_A + grp * 16384, mwbase + 16, k0, lane);
#pragma unroll
                for (int j = 0; j < 4; j++) {
                    uint32_t bh_[4], blo[4];
                    ldmB(bh_, sb + SM_W + (grp * 2 + 0) * 16384, k0, n0 + j * 16, lane);
                    ldmB(blo, sb + SM_W + (grp * 2 + 1) * 16384, k0, n0 + j * 16, lane);
#pragma unroll
                    for (int mi = 0; mi < 2; mi++) {
                        MMA_F16(acc[mi][2 * j],     a[mi], bh_[0], bh_[1]);
                        MMA_F16(acc[mi][2 * j + 1], a[mi], bh_[2], bh_[3]);
                        MMA_F16(acc[mi][2 * j],     a[mi], blo[0], blo[1]);
                        MMA_F16(acc[mi][2 * j + 1], a[mi], blo[2], blo[3]);
                    }
                }
            }
        }
    }

    // ---- epilogue ----
    int g = lane >> 2, tg = lane & 3;
    if (!write_head) {
#pragma unroll
        for (int mi = 0; mi < 2; mi++) {
            int r1 = row0 + mwbase + mi * 16 + g;
#pragma unroll
            for (int j = 0; j < 8; j++) {
                int col = n0 + j * 8 + tg * 2;
                float2 bb = *(const float2*)(bl + col);
                float o0 = fmaxf(acc[mi][j][0] + bb.x, 0.f);
                float o1 = fmaxf(acc[mi][j][1] + bb.y, 0.f);
                float o2 = fmaxf(acc[mi][j][2] + bb.x, 0.f);
                float o3 = fmaxf(acc[mi][j][3] + bb.y, 0.f);
                if (r1 < N_NODES)
                    *(uint32_t*)(hHOut + (size_t)r1 * CH + col) = h2pack(o0, o1);
                if (r1 + 8 < N_NODES)
                    *(uint32_t*)(hHOut + (size_t)(r1 + 8) * CH + col) = h2pack(o2, o3);
            }
        }
    } else {
        // fused head: partial = sum_col relu(h)*Wh[col]; out pre-initialized to bh
#pragma unroll
        for (int mi = 0; mi < 2; mi++) {
            int r1 = row0 + mwbase + mi * 16 + g;
            float p0 = 0.f, p2 = 0.f;
#pragma unroll
            for (int j = 0; j < 8; j++) {
                int col = n0 + j * 8 + tg * 2;
                float2 bb = *(const float2*)(bl + col);
                float2 wh = *(const float2*)(Wh + col);
                float o0 = fmaxf(acc[mi][j][0] + bb.x, 0.f);
                float o1 = fmaxf(acc[mi][j][1] + bb.y, 0.f);
                float o2 = fmaxf(acc[mi][j][2] + bb.x, 0.f);
                float o3 = fmaxf(acc[mi][j][3] + bb.y, 0.f);
                p0 += o0 * wh.x + o1 * wh.y;
                p2 += o2 * wh.x + o3 * wh.y;
            }
            p0 += __shfl_xor_sync(0xFFFFFFFFu, p0, 1);
            p0 += __shfl_xor_sync(0xFFFFFFFFu, p0, 2);
            p2 += __shfl_xor_sync(0xFFFFFFFFu, p2, 1);
            p2 += __shfl_xor_sync(0xFFFFFFFFu, p2, 2);
            if (tg == 0) {
                if (r1 < N_NODES) atomicAdd(out + r1, p0);
                if (r1 + 8 < N_NODES) atomicAdd(out + r1 + 8, p2);
            }
        }
    }
}

// ---------------- launch ----------------
extern "C" void kernel_launch(void* const* d_in, const int* in_sizes, int n_in,
                              void* d_out, int out_size) {
    const float* x  = (const float*)d_in[0];
    const void*  ei = d_in[1];
    const float* Wl[3] = {(const float*)d_in[2], (const float*)d_in[5], (const float*)d_in[8]};
    const float* Wr[3] = {(const float*)d_in[3], (const float*)d_in[6], (const float*)d_in[9]};
    const float* bl[3] = {(const float*)d_in[4], (const float*)d_in[7], (const float*)d_in[10]};
    const float* Wh = (const float*)d_in[11];
    const float* bh = (const float*)d_in[12];
    float* out = (float*)d_out;

    cudaFuncSetAttribute(tc_gemm_kernel, cudaFuncAttributeMaxDynamicSharedMemorySize,
                         TC_SMEM);

    void *pW, *pXH, *pAH, *pHA, *pHB;
    cudaGetSymbolAddress(&pW, g_wS);
    cudaGetSymbolAddress(&pXH, g_xH);
    cudaGetSymbolAddress(&pAH, g_aggH);
    cudaGetSymbolAddress(&pHA, g_hHA);
    cudaGetSymbolAddress(&pHB, g_hHB);
    const __half* wS = (const __half*)pW;

    init_kernel<<<(WCONV_N + XCONV_N + 255) / 256, 256>>>(
        Wl[0], Wr[0], Wl[1], Wr[1], Wl[2], Wr[2], x, bh, out, (const unsigned*)ei);
    deg_kernel<<<(N_EDGES + 255) / 256, 256>>>(ei);
    scan_kernel<<<NSCAN_BLOCKS, SCAN_BLK>>>();
    fill_kernel<<<(N_EDGES + 255) / 256, 256>>>(ei);

    const int warp_grid = (N_NODES * 32 + 255) / 256;
    const int gemm_grid = (N_NODES + 127) / 128;  // 391
    const __half* hH_in[3] = {(__half*)pXH, (__half*)pHA, (__half*)pHB};
    __half* hH_out[3] = {(__half*)pHA, (__half*)pHB, (__half*)pHA};

    for (int l = 0; l < 3; l++) {
        agg_kernel<<<warp_grid, 256>>>(hH_in[l]);
        tc_gemm_kernel<<<gemm_grid, 256, TC_SMEM>>>(
            (__half*)pAH, hH_in[l], wS + (size_t)l * 4 * 16384, bl[l], hH_out[l],
            Wh, out, (l == 2) ? 1 : 0);
    }
}

// round 12
// speedup vs baseline: 1.5746x; 1.1217x over previous
#include <cuda_runtime.h>
#include <cuda_fp16.h>
#include <cstdint>

#define N_NODES 50000
#define N_EDGES 800000
#define CH 128

#define SCAN_BLK 512
#define NSCAN_BLOCKS ((N_NODES + SCAN_BLK - 1) / SCAN_BLK)  // 98

// ---------------- device scratch (no allocations allowed) ----------------
__device__ int   g_is64;
__device__ int   g_deg[N_NODES];
__device__ int   g_rowptr[N_NODES + 1];
__device__ int   g_cursor[N_NODES];
__device__ int   g_csr[N_EDGES];
__device__ int   g_blk_agg[NSCAN_BLOCKS];
__device__ int   g_blk_inc[NSCAN_BLOCKS];
__device__ volatile int g_blk_flag[NSCAN_BLOCKS];
__device__ float g_invdeg[N_NODES];
__device__ __half g_xH [(size_t)N_NODES * CH];   // fp16 activations (layer input 0)
__device__ __half g_aggH[(size_t)N_NODES * CH];
__device__ __half g_hHA[(size_t)N_NODES * CH];   // fp16 H ping
__device__ __half g_hHB[(size_t)N_NODES * CH];   // fp16 H pong
// fp16 weights (hi only), ORIGINAL [k][n] layout: [layer][Wl, Wr]
__device__ __half g_wS[3][2][128 * 128];

// ---------------- helpers ----------------
__device__ __forceinline__ uint32_t smem_u32(const void* p) {
    uint32_t a;
    asm("{ .reg .u64 t; cvta.to.shared.u64 t, %1; cvt.u32.u64 %0, t; }"
        : "=r"(a) : "l"(p));
    return a;
}
__device__ __forceinline__ uint32_t h2pack(float a, float b) {
    return (uint32_t)__half_as_ushort(__float2half_rn(a)) |
           ((uint32_t)__half_as_ushort(__float2half_rn(b)) << 16);
}
__device__ __forceinline__ float2 h2unpack(uint32_t v) {
    __half2 h = *(__half2*)&v;
    return __half22float2(h);
}

#define MMA_F16(d, a, b0, b1) \
    asm volatile("mma.sync.aligned.m16n8k16.row.col.f32.f16.f16.f32 " \
        "{%0,%1,%2,%3}, {%4,%5,%6,%7}, {%8,%9}, {%0,%1,%2,%3};" \
        : "+f"((d)[0]), "+f"((d)[1]), "+f"((d)[2]), "+f"((d)[3]) \
        : "r"((a)[0]), "r"((a)[1]), "r"((a)[2]), "r"((a)[3]), "r"(b0), "r"(b1))

// A fragment: m16k16 from [m][k] tile (128B rows, SW128 swizzle)
__device__ __forceinline__ void ldmA(uint32_t a[4], uint32_t base, int mbase,
                                     int k0, int lane) {
    int t = lane >> 3, r = lane & 7;
    int m = mbase + (t & 1) * 8 + r;
    int kb = k0 + (t >> 1) * 8;
    uint32_t addr = base + (((uint32_t)(m * 128 + kb * 2)) ^ (uint32_t)((m & 7) << 4));
    asm volatile("ldmatrix.sync.aligned.m8n8.x4.shared.b16 {%0,%1,%2,%3}, [%4];"
                 : "=r"(a[0]), "=r"(a[1]), "=r"(a[2]), "=r"(a[3]) : "r"(addr));
}
// B fragments: two n8 tiles of k16 from [k][n] tile (256B rows, swizzled), trans
__device__ __forceinline__ void ldmB(uint32_t b[4], uint32_t base, int k0,
                                     int nb, int lane) {
    int t = lane >> 3, r = lane & 7;
    int k = k0 + (t & 1) * 8 + r;
    int n = nb + (t >> 1) * 8;
    uint32_t addr = base + (((uint32_t)(k * 256 + n * 2)) ^ (uint32_t)((k & 7) << 4));
    asm volatile("ldmatrix.sync.aligned.m8n8.x4.trans.shared.b16 {%0,%1,%2,%3}, [%4];"
                 : "=r"(b[0]), "=r"(b[1]), "=r"(b[2]), "=r"(b[3]) : "r"(addr));
}

// ---------------- init: deg zero + out=bh + flag reset + detect + conversions ----------
#define WCONV_N (3 * 2 * 128 * 128)               // 98304 weight elements
#define XCONV_N (N_NODES * CH / 2)                // 3.2M x-pairs
__global__ void init_kernel(const float* __restrict__ Wl0, const float* __restrict__ Wr0,
                            const float* __restrict__ Wl1, const float* __restrict__ Wr1,
                            const float* __restrict__ Wl2, const float* __restrict__ Wr2,
                            const float* __restrict__ x, const float* __restrict__ bh,
                            float* __restrict__ out, const unsigned* __restrict__ w) {
    int id = blockIdx.x * blockDim.x + threadIdx.x;
    if (id < N_NODES) { g_deg[id] = 0; out[id] = bh[0]; }
    if (id < NSCAN_BLOCKS) g_blk_flag[id] = 0;
    if (blockIdx.x == 0) {
        __shared__ int any32;
        if (threadIdx.x == 0) any32 = 0;
        __syncthreads();
        for (int j = threadIdx.x; j < 1024; j += blockDim.x) {
            if (w[2 * j + 1] != 0u) any32 = 1;  // benign race
        }
        __syncthreads();
        if (threadIdx.x == 0) g_is64 = any32 ? 0 : 1;
    }
    if (id < WCONV_N) {
        const float* W[3][2] = {{Wl0, Wr0}, {Wl1, Wr1}, {Wl2, Wr2}};
        int l = id / 32768;
        int rem = id % 32768;
        int mat = rem / 16384;
        int e = rem % 16384;
        g_wS[l][mat][e] = __float2half_rn(W[l][mat][e]);
    }
    int xi = id - WCONV_N;
    if (xi >= 0 && xi < XCONV_N) {
        float2 v = ((const float2*)x)[xi];
        ((uint32_t*)g_xH)[xi] = h2pack(v.x, v.y);
    }
}

__device__ __forceinline__ int load_edge(const void* ei, int idx, int is64) {
    if (is64) return (int)((const long long*)ei)[idx];
    return ((const int*)ei)[idx];
}

__global__ void deg_kernel(const void* __restrict__ ei) {
    int e = blockIdx.x * blockDim.x + threadIdx.x;
    if (e >= N_EDGES) return;
    int d = load_edge(ei, N_EDGES + e, g_is64);
    atomicAdd(&g_deg[d], 1);
}

// ---------------- single-pass decoupled-lookback scan ----------------
__global__ void scan_kernel() {
    int b = blockIdx.x, t = threadIdx.x;
    int i = b * SCAN_BLK + t;
    int lane = t & 31, wid = t >> 5;
    int d = (i < N_NODES) ? g_deg[i] : 0;
    int incl = d;
#pragma unroll
    for (int off = 1; off < 32; off <<= 1) {
        int u = __shfl_up_sync(0xFFFFFFFFu, incl, off);
        if (lane >= off) incl += u;
    }
    __shared__ int wsum[SCAN_BLK / 32];
    __shared__ int wexcl[SCAN_BLK / 32];
    __shared__ int s_excl;
    if (lane == 31) wsum[wid] = incl;
    __syncthreads();
    if (t == 0) {
        int run = 0;
#pragma unroll
        for (int w = 0; w < SCAN_BLK / 32; w++) { wexcl[w] = run; run += wsum[w]; }
        int tot = run;
        int ex = 0;
        if (b > 0) {
            g_blk_agg[b] = tot;
            __threadfence();
            g_blk_flag[b] = 1;
            for (int p = b - 1; p >= 0;) {
                int f;
                do { f = g_blk_flag[p]; } while (f == 0);
                __threadfence();
                if (f == 2) { ex += g_blk_inc[p]; break; }
                ex += g_blk_agg[p];
                p--;
            }
        }
        g_blk_inc[b] = ex + tot;
        __threadfence();
        g_blk_flag[b] = 2;
        s_excl = ex;
        if (b == NSCAN_BLOCKS - 1) g_rowptr[N_NODES] = ex + tot;
    }
    __syncthreads();
    if (i < N_NODES) {
        int exi = s_excl + wexcl[wid] + (incl - d);
        g_rowptr[i] = exi;
        g_cursor[i] = exi;
        g_invdeg[i] = (d > 0) ? (1.0f / (float)d) : 0.0f;
    }
}

__global__ void fill_kernel(const void* __restrict__ ei) {
    int e = blockIdx.x * blockDim.x + threadIdx.x;
    if (e >= N_EDGES) return;
    int is64 = g_is64;
    int s = load_edge(ei, e, is64);
    int d = load_edge(ei, N_EDGES + e, is64);
    int pos = atomicAdd(&g_cursor[d], 1);
    g_csr[pos] = s;
}

// ---------------- aggregation: one warp per node, coalesced idx + MLP8 ----------------
__global__ void agg_kernel(const __half* __restrict__ H) {
    int gt = blockIdx.x * blockDim.x + threadIdx.x;
    int node = gt >> 5;
    int lane = gt & 31;
    if (node >= N_NODES) return;
    int beg = g_rowptr[node];
    int n = g_rowptr[node + 1] - beg;

    float4 acc[8];
#pragma unroll
    for (int q = 0; q < 8; q++) acc[q] = make_float4(0.f, 0.f, 0.f, 0.f);

    const size_t laneoff = (size_t)(lane * 4);
    for (int base = 0; base < n; base += 32) {
        int cnt = n - base;
        if (cnt > 32) cnt = 32;
        int myidx = (lane < cnt) ? g_csr[beg + base + lane] : 0;
        int j = 0;
        for (; j + 8 <= cnt; j += 8) {
            int s0 = __shfl_sync(0xFFFFFFFFu, myidx, j + 0);
            int s1 = __shfl_sync(0xFFFFFFFFu, myidx, j + 1);
            int s2 = __shfl_sync(0xFFFFFFFFu, myidx, j + 2);
            int s3 = __shfl_sync(0xFFFFFFFFu, myidx, j + 3);
            int s4 = __shfl_sync(0xFFFFFFFFu, myidx, j + 4);
            int s5 = __shfl_sync(0xFFFFFFFFu, myidx, j + 5);
            int s6 = __shfl_sync(0xFFFFFFFFu, myidx, j + 6);
            int s7 = __shfl_sync(0xFFFFFFFFu, myidx, j + 7);
            uint2 r0 = *(const uint2*)(H + (size_t)s0 * CH + laneoff);
            uint2 r1 = *(const uint2*)(H + (size_t)s1 * CH + laneoff);
            uint2 r2 = *(const uint2*)(H + (size_t)s2 * CH + laneoff);
            uint2 r3 = *(const uint2*)(H + (size_t)s3 * CH + laneoff);
            uint2 r4 = *(const uint2*)(H + (size_t)s4 * CH + laneoff);
            uint2 r5 = *(const uint2*)(H + (size_t)s5 * CH + laneoff);
            uint2 r6 = *(const uint2*)(H + (size_t)s6 * CH + laneoff);
            uint2 r7 = *(const uint2*)(H + (size_t)s7 * CH + laneoff);
#define ACC(q, r) do { float2 _a = h2unpack(r.x), _b = h2unpack(r.y); \
            acc[q].x += _a.x; acc[q].y += _a.y; acc[q].z += _b.x; acc[q].w += _b.y; } while (0)
            ACC(0, r0); ACC(1, r1); ACC(2, r2); ACC(3, r3);
            ACC(4, r4); ACC(5, r5); ACC(6, r6); ACC(7, r7);
        }
        for (; j < cnt; j++) {
            int s0 = __shfl_sync(0xFFFFFFFFu, myidx, j);
            uint2 r0 = *(const uint2*)(H + (size_t)s0 * CH + laneoff);
            ACC(0, r0);
#undef ACC
        }
    }
#pragma unroll
    for (int q = 1; q < 8; q++) {
        acc[0].x += acc[q].x; acc[0].y += acc[q].y;
        acc[0].z += acc[q].z; acc[0].w += acc[q].w;
    }
    float s = g_invdeg[node];
    uint2 p;
    p.x = h2pack(acc[0].x * s, acc[0].y * s);
    p.y = h2pack(acc[0].z * s, acc[0].w * s);
    *(uint2*)(g_aggH + (size_t)node * CH + laneoff) = p;
}

// ---------------- tensor-core fused dual GEMM via mma.sync (fp16, hi-only W) --------
// Out = relu(Agg@Wl + bl + H@Wr); 2 GEMM-products per layer.
// CTA: 128x128 tile; 8 warps (4M x 2N), warp tile m32 x n64; K chunk 64.
// Last layer (write_head=1): epilogue computes logits directly into out.
#define SM_A 0                 // 2 arrays x [128][64] fp16 = 32 KB
#define SM_W 32768             // 2 mats   x [64][128] fp16 = 32 KB
#define TC_SMEM 65536

__global__ void __launch_bounds__(256, 2)
tc_gemm_kernel(const __half* __restrict__ aggH, const __half* __restrict__ hH,
               const __half* __restrict__ WS,  // [2][128*128] k-major: Wl, Wr
               const float* __restrict__ bl, __half* __restrict__ hHOut,
               const float* __restrict__ Wh, float* __restrict__ out,
               int write_head) {
    extern __shared__ char smem[];
    uint32_t sb = smem_u32(smem);
    int tid = threadIdx.x;
    int lane = tid & 31;
    int warp = tid >> 5;
    int warpM = warp & 3;
    int warpN = warp >> 2;
    int row0 = blockIdx.x * 128;
    int mwbase = warpM * 32;
    int n0 = warpN * 64;

    const __half* Asrc[2] = {aggH, hH};

    float acc[2][8][4];
#pragma unroll
    for (int mi = 0; mi < 2; mi++)
#pragma unroll
        for (int j = 0; j < 8; j++)
#pragma unroll
            for (int q = 0; q < 4; q++) acc[mi][j][q] = 0.f;

    for (int kc = 0; kc < 128; kc += 64) {
        __syncthreads();
        // stage A: 2 arrays x 128 rows x 8 units(16B)
        for (int idx = tid; idx < 2048; idx += 256) {
            int arr = idx >> 10;
            int rem = idx & 1023;
            int r = rem >> 3;
            int u = rem & 7;
            int row = row0 + r;
            uint4 v = make_uint4(0u, 0u, 0u, 0u);
            if (row < N_NODES)
                v = *(const uint4*)(Asrc[arr] + (size_t)row * CH + kc + u * 8);
            uint32_t b = (uint32_t)(r * 128 + u * 16) ^ (uint32_t)((r & 7) << 4);
            *(uint4*)(smem + SM_A + arr * 16384 + b) = v;
        }
        // stage W: 2 mats x 64 k-rows x 16 units
        for (int idx = tid; idx < 2048; idx += 256) {
            int mat = idx >> 10;
            int rem = idx & 1023;
            int k = rem >> 4;
            int u = rem & 15;
            uint4 v = *(const uint4*)(WS + mat * 16384 + (kc + k) * 128 + u * 8);
            uint32_t b = (uint32_t)(k * 256 + u * 16) ^ (uint32_t)((k & 7) << 4);
            *(uint4*)(smem + SM_W + mat * 16384 + b) = v;
        }
        __syncthreads();

#pragma unroll
        for (int k16 = 0; k16 < 4; k16++) {
            int k0 = k16 * 16;
#pragma unroll
            for (int grp = 0; grp < 2; grp++) {   // 0: agg x Wl, 1: h x Wr
                uint32_t a[2][4];
                ldmA(a[0], sb + SM_A + grp * 16384, mwbase, k0, lane);
                ldmA(a[1], sb + SM_A + grp * 16384, mwbase + 16, k0, lane);
#pragma unroll
                for (int j = 0; j < 4; j++) {
                    uint32_t bh_[4];
                    ldmB(bh_, sb + SM_W + grp * 16384, k0, n0 + j * 16, lane);
#pragma unroll
                    for (int mi = 0; mi < 2; mi++) {
                        MMA_F16(acc[mi][2 * j],     a[mi], bh_[0], bh_[1]);
                        MMA_F16(acc[mi][2 * j + 1], a[mi], bh_[2], bh_[3]);
                    }
                }
            }
        }
    }

    // ---- epilogue ----
    int g = lane >> 2, tg = lane & 3;
    if (!write_head) {
#pragma unroll
        for (int mi = 0; mi < 2; mi++) {
            int r1 = row0 + mwbase + mi * 16 + g;
#pragma unroll
            for (int j = 0; j < 8; j++) {
                int col = n0 + j * 8 + tg * 2;
                float2 bb = *(const float2*)(bl + col);
                float o0 = fmaxf(acc[mi][j][0] + bb.x, 0.f);
                float o1 = fmaxf(acc[mi][j][1] + bb.y, 0.f);
                float o2 = fmaxf(acc[mi][j][2] + bb.x, 0.f);
                float o3 = fmaxf(acc[mi][j][3] + bb.y, 0.f);
                if (r1 < N_NODES)
                    *(uint32_t*)(hHOut + (size_t)r1 * CH + col) = h2pack(o0, o1);
                if (r1 + 8 < N_NODES)
                    *(uint32_t*)(hHOut + (size_t)(r1 + 8) * CH + col) = h2pack(o2, o3);
            }
        }
    } else {
        // fused head: partial = sum_col relu(h)*Wh[col]; out pre-initialized to bh
#pragma unroll
        for (int mi = 0; mi < 2; mi++) {
            int r1 = row0 + mwbase + mi * 16 + g;
            float p0 = 0.f, p2 = 0.f;
#pragma unroll
            for (int j = 0; j < 8; j++) {
                int col = n0 + j * 8 + tg * 2;
                float2 bb = *(const float2*)(bl + col);
                float2 wh = *(const float2*)(Wh + col);
                float o0 = fmaxf(acc[mi][j][0] + bb.x, 0.f);
                float o1 = fmaxf(acc[mi][j][1] + bb.y, 0.f);
                float o2 = fmaxf(acc[mi][j][2] + bb.x, 0.f);
                float o3 = fmaxf(acc[mi][j][3] + bb.y, 0.f);
                p0 += o0 * wh.x + o1 * wh.y;
                p2 += o2 * wh.x + o3 * wh.y;
            }
            p0 += __shfl_xor_sync(0xFFFFFFFFu, p0, 1);
            p0 += __shfl_xor_sync(0xFFFFFFFFu, p0, 2);
            p2 += __shfl_xor_sync(0xFFFFFFFFu, p2, 1);
            p2 += __shfl_xor_sync(0xFFFFFFFFu, p2, 2);
            if (tg == 0) {
                if (r1 < N_NODES) atomicAdd(out + r1, p0);
                if (r1 + 8 < N_NODES) atomicAdd(out + r1 + 8, p2);
            }
        }
    }
}

// ---------------- launch ----------------
extern "C" void kernel_launch(void* const* d_in, const int* in_sizes, int n_in,
                              void* d_out, int out_size) {
    const float* x  = (const float*)d_in[0];
    const void*  ei = d_in[1];
    const float* Wl[3] = {(const float*)d_in[2], (const float*)d_in[5], (const float*)d_in[8]};
    const float* Wr[3] = {(const float*)d_in[3], (const float*)d_in[6], (const float*)d_in[9]};
    const float* bl[3] = {(const float*)d_in[4], (const float*)d_in[7], (const float*)d_in[10]};
    const float* Wh = (const float*)d_in[11];
    const float* bh = (const float*)d_in[12];
    float* out = (float*)d_out;

    cudaFuncSetAttribute(tc_gemm_kernel, cudaFuncAttributeMaxDynamicSharedMemorySize,
                         TC_SMEM);

    void *pW, *pXH, *pAH, *pHA, *pHB;
    cudaGetSymbolAddress(&pW, g_wS);
    cudaGetSymbolAddress(&pXH, g_xH);
    cudaGetSymbolAddress(&pAH, g_aggH);
    cudaGetSymbolAddress(&pHA, g_hHA);
    cudaGetSymbolAddress(&pHB, g_hHB);
    const __half* wS = (const __half*)pW;

    init_kernel<<<(WCONV_N + XCONV_N + 255) / 256, 256>>>(
        Wl[0], Wr[0], Wl[1], Wr[1], Wl[2], Wr[2], x, bh, out, (const unsigned*)ei);
    deg_kernel<<<(N_EDGES + 255) / 256, 256>>>(ei);
    scan_kernel<<<NSCAN_BLOCKS, SCAN_BLK>>>();
    fill_kernel<<<(N_EDGES + 255) / 256, 256>>>(ei);

    const int warp_grid = (N_NODES * 32 + 255) / 256;
    const int gemm_grid = (N_NODES + 127) / 128;  // 391
    const __half* hH_in[3] = {(__half*)pXH, (__half*)pHA, (__half*)pHB};
    __half* hH_out[3] = {(__half*)pHA, (__half*)pHB, (__half*)pHA};

    for (int l = 0; l < 3; l++) {
        agg_kernel<<<warp_grid, 256>>>(hH_in[l]);
        tc_gemm_kernel<<<gemm_grid, 256, TC_SMEM>>>(
            (__half*)pAH, hH_in[l], wS + (size_t)l * 2 * 16384, bl[l], hH_out[l],
            Wh, out, (l == 2) ? 1 : 0);
    }
}

// round 13
// speedup vs baseline: 1.6739x; 1.0631x over previous
#include <cuda_runtime.h>
#include <cuda_fp16.h>
#include <cstdint>

#define N_NODES 50000
#define N_EDGES 800000
#define CH 128

#define SCAN_BLK 512
#define NSCAN_BLOCKS ((N_NODES + SCAN_BLK - 1) / SCAN_BLK)  // 98

// ---------------- device scratch (no allocations allowed) ----------------
__device__ int   g_is64;
__device__ int   g_deg[N_NODES];
__device__ int   g_rowptr[N_NODES + 1];
__device__ int   g_cursor[N_NODES];
__device__ int   g_csr[N_EDGES];
__device__ int   g_blk_agg[NSCAN_BLOCKS];
__device__ int   g_blk_inc[NSCAN_BLOCKS];
__device__ volatile int g_blk_flag[NSCAN_BLOCKS];
__device__ float g_invdeg[N_NODES];
__device__ __half g_xH [(size_t)N_NODES * CH];   // fp16 activations (layer input 0)
__device__ __half g_aggH[(size_t)N_NODES * CH];
__device__ __half g_hHA[(size_t)N_NODES * CH];   // fp16 H ping
__device__ __half g_hHB[(size_t)N_NODES * CH];   // fp16 H pong
// fp16 weights, ORIGINAL [k][n] layout: [layer][Wl, Wr]
__device__ __half g_wS[3][2][128 * 128];

// ---------------- helpers ----------------
__device__ __forceinline__ uint32_t smem_u32(const void* p) {
    uint32_t a;
    asm("{ .reg .u64 t; cvta.to.shared.u64 t, %1; cvt.u32.u64 %0, t; }"
        : "=r"(a) : "l"(p));
    return a;
}
__device__ __forceinline__ uint32_t h2pack(float a, float b) {
    return (uint32_t)__half_as_ushort(__float2half_rn(a)) |
           ((uint32_t)__half_as_ushort(__float2half_rn(b)) << 16);
}
__device__ __forceinline__ float2 h2unpack(uint32_t v) {
    __half2 h = *(__half2*)&v;
    return __half22float2(h);
}

#define MMA_F16(d, a, b0, b1) \
    asm volatile("mma.sync.aligned.m16n8k16.row.col.f32.f16.f16.f32 " \
        "{%0,%1,%2,%3}, {%4,%5,%6,%7}, {%8,%9}, {%0,%1,%2,%3};" \
        : "+f"((d)[0]), "+f"((d)[1]), "+f"((d)[2]), "+f"((d)[3]) \
        : "r"((a)[0]), "r"((a)[1]), "r"((a)[2]), "r"((a)[3]), "r"(b0), "r"(b1))

// A fragment: m16k16 from [m][k] tile (128B rows, SW128 swizzle)
__device__ __forceinline__ void ldmA(uint32_t a[4], uint32_t base, int mbase,
                                     int k0, int lane) {
    int t = lane >> 3, r = lane & 7;
    int m = mbase + (t & 1) * 8 + r;
    int kb = k0 + (t >> 1) * 8;
    uint32_t addr = base + (((uint32_t)(m * 128 + kb * 2)) ^ (uint32_t)((m & 7) << 4));
    asm volatile("ldmatrix.sync.aligned.m8n8.x4.shared.b16 {%0,%1,%2,%3}, [%4];"
                 : "=r"(a[0]), "=r"(a[1]), "=r"(a[2]), "=r"(a[3]) : "r"(addr));
}
// B fragments: two n8 tiles of k16 from [k][n] tile (256B rows, swizzled), trans
__device__ __forceinline__ void ldmB(uint32_t b[4], uint32_t base, int k0,
                                     int nb, int lane) {
    int t = lane >> 3, r = lane & 7;
    int k = k0 + (t & 1) * 8 + r;
    int n = nb + (t >> 1) * 8;
    uint32_t addr = base + (((uint32_t)(k * 256 + n * 2)) ^ (uint32_t)((k & 7) << 4));
    asm volatile("ldmatrix.sync.aligned.m8n8.x4.trans.shared.b16 {%0,%1,%2,%3}, [%4];"
                 : "=r"(b[0]), "=r"(b[1]), "=r"(b[2]), "=r"(b[3]) : "r"(addr));
}

// ---------------- init: deg zero + out=bh + flag reset + detect + conversions ----------
#define WCONV_N (3 * 2 * 128 * 128)               // 98304 weight elements
#define XCONV_N (N_NODES * CH / 2)                // 3.2M x-pairs
__global__ void init_kernel(const float* __restrict__ Wl0, const float* __restrict__ Wr0,
                            const float* __restrict__ Wl1, const float* __restrict__ Wr1,
                            const float* __restrict__ Wl2, const float* __restrict__ Wr2,
                            const float* __restrict__ x, const float* __restrict__ bh,
                            float* __restrict__ out, const unsigned* __restrict__ w) {
    int id = blockIdx.x * blockDim.x + threadIdx.x;
    if (id < N_NODES) { g_deg[id] = 0; out[id] = bh[0]; }
    if (id < NSCAN_BLOCKS) g_blk_flag[id] = 0;
    if (blockIdx.x == 0) {
        __shared__ int any32;
        if (threadIdx.x == 0) any32 = 0;
        __syncthreads();
        for (int j = threadIdx.x; j < 1024; j += blockDim.x) {
            if (w[2 * j + 1] != 0u) any32 = 1;  // benign race
        }
        __syncthreads();
        if (threadIdx.x == 0) g_is64 = any32 ? 0 : 1;
    }
    if (id < WCONV_N) {
        const float* W[3][2] = {{Wl0, Wr0}, {Wl1, Wr1}, {Wl2, Wr2}};
        int l = id / 32768;
        int rem = id % 32768;
        int mat = rem / 16384;
        int e = rem % 16384;
        g_wS[l][mat][e] = __float2half_rn(W[l][mat][e]);
    }
    int xi = id - WCONV_N;
    if (xi >= 0 && xi < XCONV_N) {
        float2 v = ((const float2*)x)[xi];
        ((uint32_t*)g_xH)[xi] = h2pack(v.x, v.y);
    }
}

__device__ __forceinline__ int load_edge(const void* ei, int idx, int is64) {
    if (is64) return (int)((const long long*)ei)[idx];
    return ((const int*)ei)[idx];
}

__global__ void deg_kernel(const void* __restrict__ ei) {
    int e = blockIdx.x * blockDim.x + threadIdx.x;
    if (e >= N_EDGES) return;
    int d = load_edge(ei, N_EDGES + e, g_is64);
    atomicAdd(&g_deg[d], 1);
}

// ---------------- single-pass decoupled-lookback scan ----------------
__global__ void scan_kernel() {
    int b = blockIdx.x, t = threadIdx.x;
    int i = b * SCAN_BLK + t;
    int lane = t & 31, wid = t >> 5;
    int d = (i < N_NODES) ? g_deg[i] : 0;
    int incl = d;
#pragma unroll
    for (int off = 1; off < 32; off <<= 1) {
        int u = __shfl_up_sync(0xFFFFFFFFu, incl, off);
        if (lane >= off) incl += u;
    }
    __shared__ int wsum[SCAN_BLK / 32];
    __shared__ int wexcl[SCAN_BLK / 32];
    __shared__ int s_excl;
    if (lane == 31) wsum[wid] = incl;
    __syncthreads();
    if (t == 0) {
        int run = 0;
#pragma unroll
        for (int w = 0; w < SCAN_BLK / 32; w++) { wexcl[w] = run; run += wsum[w]; }
        int tot = run;
        int ex = 0;
        if (b > 0) {
            g_blk_agg[b] = tot;
            __threadfence();
            g_blk_flag[b] = 1;
            for (int p = b - 1; p >= 0;) {
                int f;
                do { f = g_blk_flag[p]; } while (f == 0);
                __threadfence();
                if (f == 2) { ex += g_blk_inc[p]; break; }
                ex += g_blk_agg[p];
                p--;
            }
        }
        g_blk_inc[b] = ex + tot;
        __threadfence();
        g_blk_flag[b] = 2;
        s_excl = ex;
        if (b == NSCAN_BLOCKS - 1) g_rowptr[N_NODES] = ex + tot;
    }
    __syncthreads();
    if (i < N_NODES) {
        int exi = s_excl + wexcl[wid] + (incl - d);
        g_rowptr[i] = exi;
        g_cursor[i] = exi;
        g_invdeg[i] = (d > 0) ? (1.0f / (float)d) : 0.0f;
    }
}

__global__ void fill_kernel(const void* __restrict__ ei) {
    int e = blockIdx.x * blockDim.x + threadIdx.x;
    if (e >= N_EDGES) return;
    int is64 = g_is64;
    int s = load_edge(ei, e, is64);
    int d = load_edge(ei, N_EDGES + e, is64);
    int pos = atomicAdd(&g_cursor[d], 1);
    g_csr[pos] = s;
}

// ---------------- aggregation: one warp per node, 2 edges per LDG.128 --------------
// Half-warp scheme: lanes 0-15 cover edge e0's full 256B row (16B/lane),
// lanes 16-31 cover edge e1. 4 pair-loads (8 edges) in flight per iteration.
// Final cross-half-warp shfl(16) reduction; lanes 0-15 store the 256B output row.
__global__ void agg_kernel(const __half* __restrict__ H) {
    int gt = blockIdx.x * blockDim.x + threadIdx.x;
    int node = gt >> 5;
    int lane = gt & 31;
    if (node >= N_NODES) return;
    int beg = g_rowptr[node];
    int n = g_rowptr[node + 1] - beg;

    int half = lane >> 4;        // 0 or 1: which edge of the pair
    int sub = lane & 15;         // 16B-chunk within the row

    float acc[4][8];
#pragma unroll
    for (int p = 0; p < 4; p++)
#pragma unroll
        for (int q = 0; q < 8; q++) acc[p][q] = 0.f;

#define UNPACK8(dst, v) do {                                    \
    float2 _f0 = h2unpack((v).x), _f1 = h2unpack((v).y);        \
    float2 _f2 = h2unpack((v).z), _f3 = h2unpack((v).w);        \
    dst[0] += _f0.x; dst[1] += _f0.y; dst[2] += _f1.x;          \
    dst[3] += _f1.y; dst[4] += _f2.x; dst[5] += _f2.y;          \
    dst[6] += _f3.x; dst[7] += _f3.y; } while (0)

    for (int base = 0; base < n; base += 32) {
        int cnt = n - base;
        if (cnt > 32) cnt = 32;
        int myidx = (lane < cnt) ? g_csr[beg + base + lane] : 0;
        int j = 0;
        for (; j + 8 <= cnt; j += 8) {
            int e0 = j + 0 + half, e1 = j + 2 + half;
            int e2 = j + 4 + half, e3 = j + 6 + half;
            int s0 = __shfl_sync(0xFFFFFFFFu, myidx, e0);
            int s1 = __shfl_sync(0xFFFFFFFFu, myidx, e1);
            int s2 = __shfl_sync(0xFFFFFFFFu, myidx, e2);
            int s3 = __shfl_sync(0xFFFFFFFFu, myidx, e3);
            uint4 v0 = *(const uint4*)(H + (size_t)s0 * CH + sub * 8);
            uint4 v1 = *(const uint4*)(H + (size_t)s1 * CH + sub * 8);
            uint4 v2 = *(const uint4*)(H + (size_t)s2 * CH + sub * 8);
            uint4 v3 = *(const uint4*)(H + (size_t)s3 * CH + sub * 8);
            UNPACK8(acc[0], v0);
            UNPACK8(acc[1], v1);
            UNPACK8(acc[2], v2);
            UNPACK8(acc[3], v3);
        }
        for (; j < cnt; j += 2) {
            int e = j + half;
            int valid = (e < cnt);
            int ee = valid ? e : j;
            int s0 = __shfl_sync(0xFFFFFFFFu, myidx, ee);
            uint4 v0 = *(const uint4*)(H + (size_t)s0 * CH + sub * 8);
            if (valid) UNPACK8(acc[0], v0);
        }
    }
#undef UNPACK8

    // combine the 4 pipelined accumulators
#pragma unroll
    for (int p = 1; p < 4; p++)
#pragma unroll
        for (int q = 0; q < 8; q++) acc[0][q] += acc[p][q];
    // cross-half-warp reduce (lane L gets lane L+16's partial)
#pragma unroll
    for (int q = 0; q < 8; q++)
        acc[0][q] += __shfl_down_sync(0xFFFFFFFFu, acc[0][q], 16);

    if (lane < 16) {
        float s = g_invdeg[node];
        uint4 p;
        p.x = h2pack(acc[0][0] * s, acc[0][1] * s);
        p.y = h2pack(acc[0][2] * s, acc[0][3] * s);
        p.z = h2pack(acc[0][4] * s, acc[0][5] * s);
        p.w = h2pack(acc[0][6] * s, acc[0][7] * s);
        *(uint4*)(g_aggH + (size_t)node * CH + sub * 8) = p;
    }
}

// ---------------- tensor-core fused dual GEMM via mma.sync (fp16) ----------------
// Out = relu(Agg@Wl + bl + H@Wr); 2 GEMM-products per layer.
// CTA: 128x128 tile; 8 warps (4M x 2N), warp tile m32 x n64; K chunk 64.
// Last layer (write_head=1): epilogue computes logits directly into out.
#define SM_A 0                 // 2 arrays x [128][64] fp16 = 32 KB
#define SM_W 32768             // 2 mats   x [64][128] fp16 = 32 KB
#define TC_SMEM 65536

__global__ void __launch_bounds__(256, 2)
tc_gemm_kernel(const __half* __restrict__ aggH, const __half* __restrict__ hH,
               const __half* __restrict__ WS,  // [2][128*128] k-major: Wl, Wr
               const float* __restrict__ bl, __half* __restrict__ hHOut,
               const float* __restrict__ Wh, float* __restrict__ out,
               int write_head) {
    extern __shared__ char smem[];
    uint32_t sb = smem_u32(smem);
    int tid = threadIdx.x;
    int lane = tid & 31;
    int warp = tid >> 5;
    int warpM = warp & 3;
    int warpN = warp >> 2;
    int row0 = blockIdx.x * 128;
    int mwbase = warpM * 32;
    int n0 = warpN * 64;

    const __half* Asrc[2] = {aggH, hH};

    float acc[2][8][4];
#pragma unroll
    for (int mi = 0; mi < 2; mi++)
#pragma unroll
        for (int j = 0; j < 8; j++)
#pragma unroll
            for (int q = 0; q < 4; q++) acc[mi][j][q] = 0.f;

    for (int kc = 0; kc < 128; kc += 64) {
        __syncthreads();
        // stage A: 2 arrays x 128 rows x 8 units(16B)
        for (int idx = tid; idx < 2048; idx += 256) {
            int arr = idx >> 10;
            int rem = idx & 1023;
            int r = rem >> 3;
            int u = rem & 7;
            int row = row0 + r;
            uint4 v = make_uint4(0u, 0u, 0u, 0u);
            if (row < N_NODES)
                v = *(const uint4*)(Asrc[arr] + (size_t)row * CH + kc + u * 8);
            uint32_t b = (uint32_t)(r * 128 + u * 16) ^ (uint32_t)((r & 7) << 4);
            *(uint4*)(smem + SM_A + arr * 16384 + b) = v;
        }
        // stage W: 2 mats x 64 k-rows x 16 units
        for (int idx = tid; idx < 2048; idx += 256) {
            int mat = idx >> 10;
            int rem = idx & 1023;
            int k = rem >> 4;
            int u = rem & 15;
            uint4 v = *(const uint4*)(WS + mat * 16384 + (kc + k) * 128 + u * 8);
            uint32_t b = (uint32_t)(k * 256 + u * 16) ^ (uint32_t)((k & 7) << 4);
            *(uint4*)(smem + SM_W + mat * 16384 + b) = v;
        }
        __syncthreads();

#pragma unroll
        for (int k16 = 0; k16 < 4; k16++) {
            int k0 = k16 * 16;
#pragma unroll
            for (int grp = 0; grp < 2; grp++) {   // 0: agg x Wl, 1: h x Wr
                uint32_t a[2][4];
                ldmA(a[0], sb + SM_A + grp * 16384, mwbase, k0, lane);
                ldmA(a[1], sb + SM_A + grp * 16384, mwbase + 16, k0, lane);
#pragma unroll
                for (int j = 0; j < 4; j++) {
                    uint32_t bh_[4];
                    ldmB(bh_, sb + SM_W + grp * 16384, k0, n0 + j * 16, lane);
#pragma unroll
                    for (int mi = 0; mi < 2; mi++) {
                        MMA_F16(acc[mi][2 * j],     a[mi], bh_[0], bh_[1]);
                        MMA_F16(acc[mi][2 * j + 1], a[mi], bh_[2], bh_[3]);
                    }
                }
            }
        }
    }

    // ---- epilogue ----
    int g = lane >> 2, tg = lane & 3;
    if (!write_head) {
#pragma unroll
        for (int mi = 0; mi < 2; mi++) {
            int r1 = row0 + mwbase + mi * 16 + g;
#pragma unroll
            for (int j = 0; j < 8; j++) {
                int col = n0 + j * 8 + tg * 2;
                float2 bb = *(const float2*)(bl + col);
                float o0 = fmaxf(acc[mi][j][0] + bb.x, 0.f);
                float o1 = fmaxf(acc[mi][j][1] + bb.y, 0.f);
                float o2 = fmaxf(acc[mi][j][2] + bb.x, 0.f);
                float o3 = fmaxf(acc[mi][j][3] + bb.y, 0.f);
                if (r1 < N_NODES)
                    *(uint32_t*)(hHOut + (size_t)r1 * CH + col) = h2pack(o0, o1);
                if (r1 + 8 < N_NODES)
                    *(uint32_t*)(hHOut + (size_t)(r1 + 8) * CH + col) = h2pack(o2, o3);
            }
        }
    } else {
        // fused head: partial = sum_col relu(h)*Wh[col]; out pre-initialized to bh
#pragma unroll
        for (int mi = 0; mi < 2; mi++) {
            int r1 = row0 + mwbase + mi * 16 + g;
            float p0 = 0.f, p2 = 0.f;
#pragma unroll
            for (int j = 0; j < 8; j++) {
                int col = n0 + j * 8 + tg * 2;
                float2 bb = *(const float2*)(bl + col);
                float2 wh = *(const float2*)(Wh + col);
                float o0 = fmaxf(acc[mi][j][0] + bb.x, 0.f);
                float o1 = fmaxf(acc[mi][j][1] + bb.y, 0.f);
                float o2 = fmaxf(acc[mi][j][2] + bb.x, 0.f);
                float o3 = fmaxf(acc[mi][j][3] + bb.y, 0.f);
                p0 += o0 * wh.x + o1 * wh.y;
                p2 += o2 * wh.x + o3 * wh.y;
            }
            p0 += __shfl_xor_sync(0xFFFFFFFFu, p0, 1);
            p0 += __shfl_xor_sync(0xFFFFFFFFu, p0, 2);
            p2 += __shfl_xor_sync(0xFFFFFFFFu, p2, 1);
            p2 += __shfl_xor_sync(0xFFFFFFFFu, p2, 2);
            if (tg == 0) {
                if (r1 < N_NODES) atomicAdd(out + r1, p0);
                if (r1 + 8 < N_NODES) atomicAdd(out + r1 + 8, p2);
            }
        }
    }
}

// ---------------- launch ----------------
extern "C" void kernel_launch(void* const* d_in, const int* in_sizes, int n_in,
                              void* d_out, int out_size) {
    const float* x  = (const float*)d_in[0];
    const void*  ei = d_in[1];
    const float* Wl[3] = {(const float*)d_in[2], (const float*)d_in[5], (const float*)d_in[8]};
    const float* Wr[3] = {(const float*)d_in[3], (const float*)d_in[6], (const float*)d_in[9]};
    const float* bl[3] = {(const float*)d_in[4], (const float*)d_in[7], (const float*)d_in[10]};
    const float* Wh = (const float*)d_in[11];
    const float* bh = (const float*)d_in[12];
    float* out = (float*)d_out;

    cudaFuncSetAttribute(tc_gemm_kernel, cudaFuncAttributeMaxDynamicSharedMemorySize,
                         TC_SMEM);

    void *pW, *pXH, *pAH, *pHA, *pHB;
    cudaGetSymbolAddress(&pW, g_wS);
    cudaGetSymbolAddress(&pXH, g_xH);
    cudaGetSymbolAddress(&pAH, g_aggH);
    cudaGetSymbolAddress(&pHA, g_hHA);
    cudaGetSymbolAddress(&pHB, g_hHB);
    const __half* wS = (const __half*)pW;

    init_kernel<<<(WCONV_N + XCONV_N + 255) / 256, 256>>>(
        Wl[0], Wr[0], Wl[1], Wr[1], Wl[2], Wr[2], x, bh, out, (const unsigned*)ei);
    deg_kernel<<<(N_EDGES + 255) / 256, 256>>>(ei);
    scan_kernel<<<NSCAN_BLOCKS, SCAN_BLK>>>();
    fill_kernel<<<(N_EDGES + 255) / 256, 256>>>(ei);

    const int agg_grid = (N_NODES * 32 + 63) / 64;   // 64-thread CTAs: finer retire granularity
    const int gemm_grid = (N_NODES + 127) / 128;     // 391
    const __half* hH_in[3] = {(__half*)pXH, (__half*)pHA, (__half*)pHB};
    __half* hH_out[3] = {(__half*)pHA, (__half*)pHB, (__half*)pHA};

    for (int l = 0; l < 3; l++) {
        agg_kernel<<<agg_grid, 64>>>(hH_in[l]);
        tc_gemm_kernel<<<gemm_grid, 256, TC_SMEM>>>(
            (__half*)pAH, hH_in[l], wS + (size_t)l * 2 * 16384, bl[l], hH_out[l],
            Wh, out, (l == 2) ? 1 : 0);
    }
}